// round 2
// baseline (speedup 1.0000x reference)
#include <cuda_runtime.h>
#include <math.h>

#define D 70
#define NMAX 50000
#define EMAX 800000
#define GG 128

// ---------------- device scratch ----------------
__device__ float g_h[NMAX * D];
__device__ float g_A[NMAX * D];
__device__ float g_B[NMAX * D];
__device__ float g_Dh[NMAX * D];
__device__ float g_Eh[NMAX * D];
__device__ float g_hraw[NMAX * D];
__device__ float g_nd[NMAX * 2 * D];      // interleaved (num, den) pairs
__device__ float g_e[EMAX * D];
__device__ float g_enew[EMAX * D];
__device__ double g_stats[4 * D];          // hsum, hsq, esum, esq
__device__ float g_norm[4 * D];            // mu_h, rstd_h, mu_e, rstd_e
__device__ float g_hg[GG * D];
__device__ float g_cnt[GG];
__device__ float g_u[D];                   // rank-1 Ce for layer 0
__device__ float g_v[D];

__device__ __forceinline__ void red_add_v2(float* addr, float a, float b) {
    asm volatile("red.global.add.v2.f32 [%0], {%1, %2};"
                 :: "l"(addr), "f"(a), "f"(b) : "memory");
}

// ---------------- zero kernels ----------------
__global__ void zero_layer_kernel(int n2) {
    int i = blockIdx.x * blockDim.x + threadIdx.x;
    int stride = gridDim.x * blockDim.x;
    for (int idx = i; idx < n2; idx += stride) g_nd[idx] = 0.f;
    if (i < 4 * D) g_stats[i] = 0.0;
}

__global__ void zero_readout_kernel() {
    int i = blockIdx.x * blockDim.x + threadIdx.x;
    if (i < GG * D) g_hg[i] = 0.f;
    if (i < GG) g_cnt[i] = 0.f;
}

// ---------------- rank-1 layer-0 Ce precompute ----------------
__global__ void uv_kernel(const float* __restrict__ WembE, const float* __restrict__ bembE,
                          const float* __restrict__ WC, const float* __restrict__ bC) {
    int j = threadIdx.x;
    if (j >= D) return;
    float u = 0.f, v = 0.f;
    for (int k = 0; k < D; k++) {
        float w = WC[k * D + j];
        u += WembE[k] * w;
        v += bembE[k] * w;
    }
    g_u[j] = u;
    g_v[j] = v + bC[j];
}

// ---------------- embedding GEMM [N,146]@[146,70] ----------------
template <int K>
__global__ void gemm70_kernel(const float* __restrict__ X, const float* __restrict__ W,
                              const float* __restrict__ bias, float* __restrict__ Y, int M) {
    extern __shared__ float smem[];
    float* sW = smem;            // K*70
    float* sX = smem + K * D;    // 64*K
    __shared__ float sb[D];
    const int tx = threadIdx.x, ty = threadIdx.y;
    const int tid = ty * 14 + tx;
    for (int i = tid; i < K * D; i += 224) sW[i] = W[i];
    if (tid < D) sb[tid] = bias[tid];
    __syncthreads();

    const int base = blockIdx.x * 64;
    const int cnt = min(64, M - base);
    for (int i = tid; i < cnt * K; i += 224) sX[i] = X[(size_t)base * K + i];
    __syncthreads();

    const int c0 = tx * 5, r0 = ty * 4;
    float acc[4][5];
#pragma unroll
    for (int r = 0; r < 4; r++)
#pragma unroll
        for (int c = 0; c < 5; c++) acc[r][c] = sb[c0 + c];

#pragma unroll 2
    for (int k = 0; k < K; k++) {
        float w0 = sW[k * D + c0 + 0], w1 = sW[k * D + c0 + 1], w2 = sW[k * D + c0 + 2];
        float w3 = sW[k * D + c0 + 3], w4 = sW[k * D + c0 + 4];
#pragma unroll
        for (int r = 0; r < 4; r++) {
            float xv = (r0 + r < cnt) ? sX[(r0 + r) * K + k] : 0.f;
            acc[r][0] += xv * w0; acc[r][1] += xv * w1; acc[r][2] += xv * w2;
            acc[r][3] += xv * w3; acc[r][4] += xv * w4;
        }
    }
#pragma unroll
    for (int r = 0; r < 4; r++) {
        int row = base + r0 + r;
        if (row < M) {
#pragma unroll
            for (int c = 0; c < 5; c++) Y[(size_t)row * D + c0 + c] = acc[r][c];
        }
    }
}

// ---------------- fused node kernel: optional h-update + 4 GEMMs ----------------
__global__ __launch_bounds__(224) void gemm4_kernel(
    const float* __restrict__ WA, const float* __restrict__ bA,
    const float* __restrict__ WB, const float* __restrict__ bB,
    const float* __restrict__ WD, const float* __restrict__ bD,
    const float* __restrict__ WE, const float* __restrict__ bE,
    const float* __restrict__ hgam, const float* __restrict__ hbet,
    int fuse, int Nn) {
    __shared__ float sX[64 * D];
    __shared__ float sW[D * D];
    __shared__ float sb[D];
    __shared__ float sMu[D], sRs[D], sGa[D], sBe[D];
    const int tx = threadIdx.x, ty = threadIdx.y;
    const int tid = ty * 14 + tx;
    if (fuse && tid < D) {
        sMu[tid] = g_norm[tid];
        sRs[tid] = g_norm[D + tid];
        sGa[tid] = hgam[tid];
        sBe[tid] = hbet[tid];
    }
    const int base = blockIdx.x * 64;
    const int cnt = min(64, Nn - base);
    __syncthreads();
    for (int idx = tid; idx < cnt * D; idx += 224) {
        size_t gi = (size_t)base * D + idx;
        float v = g_h[gi];
        if (fuse) {
            int r = idx / D;
            int c = idx - r * D;
            float hr = g_hraw[gi];
            v += fmaxf((hr - sMu[c]) * sRs[c] * sGa[c] + sBe[c], 0.f);
            g_h[gi] = v;
        }
        sX[idx] = v;
    }
    if (cnt < 64)
        for (int idx = cnt * D + tid; idx < 64 * D; idx += 224) sX[idx] = 0.f;

    const float* Ws[4] = {WA, WB, WD, WE};
    const float* bs[4] = {bA, bB, bD, bE};
    float* outs[4] = {g_A, g_B, g_Dh, g_Eh};

    const int c0 = tx * 5, r0 = ty * 4;
    for (int m = 0; m < 4; m++) {
        __syncthreads();
        for (int i = tid; i < D * D; i += 224) sW[i] = Ws[m][i];
        if (tid < D) sb[tid] = bs[m][tid];
        __syncthreads();

        float acc[4][5];
#pragma unroll
        for (int r = 0; r < 4; r++)
#pragma unroll
            for (int c = 0; c < 5; c++) acc[r][c] = sb[c0 + c];

#pragma unroll 2
        for (int k = 0; k < D; k++) {
            float w0 = sW[k * D + c0 + 0], w1 = sW[k * D + c0 + 1], w2 = sW[k * D + c0 + 2];
            float w3 = sW[k * D + c0 + 3], w4 = sW[k * D + c0 + 4];
#pragma unroll
            for (int r = 0; r < 4; r++) {
                float xv = sX[(r0 + r) * D + k];
                acc[r][0] += xv * w0; acc[r][1] += xv * w1; acc[r][2] += xv * w2;
                acc[r][3] += xv * w3; acc[r][4] += xv * w4;
            }
        }
        float* out = outs[m];
#pragma unroll
        for (int r = 0; r < 4; r++) {
            int row = base + r0 + r;
            if (row < cnt + base) {
#pragma unroll
                for (int c = 0; c < 5; c++) out[(size_t)row * D + c0 + c] = acc[r][c];
            }
        }
    }
}

// ---------------- layer-0 edge kernel (rank-1 Ce, no GEMM) ----------------
__global__ __launch_bounds__(560) void edge0_kernel(
    const float* __restrict__ ef, const int* __restrict__ src, const int* __restrict__ dst,
    const float* __restrict__ snorm_e, int E_) {
    int j = threadIdx.x, ty = threadIdx.y;  // (70, 8)
    float u = g_u[j], v = g_v[j];
    float ls = 0.f, lq = 0.f;
    for (int ei = blockIdx.x * 8 + ty; ei < E_; ei += gridDim.x * 8) {
        int s = src[ei], d2 = dst[ei];
        float en = ef[ei] * u + v + g_Dh[(size_t)s * D + j] + g_Eh[(size_t)d2 * D + j];
        float sg = 1.f / (1.f + __expf(-en));
        red_add_v2(&g_nd[(size_t)d2 * 2 * D + 2 * j], g_B[(size_t)s * D + j] * sg, sg);
        float ens = en * snorm_e[ei];
        g_enew[(size_t)ei * D + j] = ens;
        ls += ens; lq += ens * ens;
    }
    __shared__ float s1[8][D];
    s1[ty][j] = ls;
    __syncthreads();
    if (ty == 0) {
        float s = ls;
        for (int yy = 1; yy < 8; yy++) s += s1[yy][j];
        atomicAdd(&g_stats[2 * D + j], (double)s);
    }
    __syncthreads();
    s1[ty][j] = lq;
    __syncthreads();
    if (ty == 0) {
        float s = lq;
        for (int yy = 1; yy < 8; yy++) s += s1[yy][j];
        atomicAdd(&g_stats[3 * D + j], (double)s);
    }
}

// ---------------- fused edge kernel for layers 1..3 ----------------
// Reconstruct e_l = e_prev + relu(bn(enew_prev)) into smem (+ optional writeback),
// GEMM Ce = e_l @ WC + bC, gather Dh/Eh, sigmoid, v2 reductions, optional enew store + stats.
template <int RANK1E, int WRITE_E, int STORE_E>
__global__ __launch_bounds__(224) void edge_kernel(
    const float* __restrict__ ef,
    const float* __restrict__ WC, const float* __restrict__ bC,
    const float* __restrict__ embW, const float* __restrict__ embB,
    const float* __restrict__ egam, const float* __restrict__ ebet,
    const int* __restrict__ src, const int* __restrict__ dst,
    const float* __restrict__ snorm_e, int E_) {
    extern __shared__ __align__(16) float dsm[];
    float* sX = dsm;               // 128*70
    float* sW = dsm + 128 * D;     // 70*70
    __shared__ float sb[D];
    __shared__ int sS[128], sT[128];
    __shared__ float sMu[D], sRs[D], sGa[D], sBe[D], sEW[D], sEB[D];
    const int tx = threadIdx.x, ty = threadIdx.y;
    const int tid = ty * 14 + tx;
    for (int i = tid; i < D * D; i += 224) sW[i] = WC[i];
    if (tid < D) {
        sb[tid] = bC[tid];
        sMu[tid] = g_norm[2 * D + tid];
        sRs[tid] = g_norm[3 * D + tid];
        sGa[tid] = egam[tid];
        sBe[tid] = ebet[tid];
        if (RANK1E) { sEW[tid] = embW[tid]; sEB[tid] = embB[tid]; }
    }
    __syncthreads();

    const int c0 = tx * 5, r0 = ty * 8;
    float lsum[5] = {0, 0, 0, 0, 0}, lsq[5] = {0, 0, 0, 0, 0};

    for (int base = blockIdx.x * 128; base < E_; base += gridDim.x * 128) {
        int cnt = min(128, E_ - base);
        for (int idx = tid; idx < cnt * D; idx += 224) {
            size_t gi = (size_t)base * D + idx;
            int r = idx / D;
            int c = idx - r * D;
            float en = g_enew[gi];
            float e0;
            if (RANK1E) e0 = ef[base + r] * sEW[c] + sEB[c];
            else        e0 = g_e[gi];
            float val = e0 + fmaxf((en - sMu[c]) * sRs[c] * sGa[c] + sBe[c], 0.f);
            sX[idx] = val;
            if (WRITE_E) g_e[gi] = val;
        }
        if (cnt < 128)
            for (int idx = cnt * D + tid; idx < 128 * D; idx += 224) sX[idx] = 0.f;
        for (int i = tid; i < cnt; i += 224) { sS[i] = src[base + i]; sT[i] = dst[base + i]; }
        __syncthreads();

        float acc[8][5];
#pragma unroll
        for (int r = 0; r < 8; r++)
#pragma unroll
            for (int c = 0; c < 5; c++) acc[r][c] = sb[c0 + c];

#pragma unroll 2
        for (int k = 0; k < D; k++) {
            float w0 = sW[k * D + c0 + 0], w1 = sW[k * D + c0 + 1], w2 = sW[k * D + c0 + 2];
            float w3 = sW[k * D + c0 + 3], w4 = sW[k * D + c0 + 4];
#pragma unroll
            for (int r = 0; r < 8; r++) {
                float xv = sX[(r0 + r) * D + k];
                acc[r][0] += xv * w0; acc[r][1] += xv * w1; acc[r][2] += xv * w2;
                acc[r][3] += xv * w3; acc[r][4] += xv * w4;
            }
        }

#pragma unroll
        for (int r = 0; r < 8; r++) {
            int ei = base + r0 + r;
            if (ei < E_) {
                int s = sS[r0 + r], d2 = sT[r0 + r];
                const float* dhp = g_Dh + (size_t)s * D + c0;
                const float* ehp = g_Eh + (size_t)d2 * D + c0;
                const float* bhp = g_B + (size_t)s * D + c0;
                float* ndp = g_nd + (size_t)d2 * 2 * D + 2 * c0;
                float sn = STORE_E ? snorm_e[ei] : 0.f;
#pragma unroll
                for (int c = 0; c < 5; c++) {
                    float en = acc[r][c] + dhp[c] + ehp[c];
                    float sg = 1.f / (1.f + __expf(-en));
                    red_add_v2(ndp + 2 * c, bhp[c] * sg, sg);
                    if (STORE_E) {
                        float ens = en * sn;
                        g_enew[(size_t)ei * D + c0 + c] = ens;
                        lsum[c] += ens; lsq[c] += ens * ens;
                    }
                }
            }
        }
        __syncthreads();
    }

    if (STORE_E) {
        double* dsc = (double*)dsm;  // 16*70 doubles = 8960B
#pragma unroll
        for (int c = 0; c < 5; c++) dsc[ty * D + c0 + c] = (double)lsum[c];
        __syncthreads();
        if (ty == 0) {
#pragma unroll
            for (int c = 0; c < 5; c++) {
                double s = 0;
                for (int yy = 0; yy < 16; yy++) s += dsc[yy * D + c0 + c];
                atomicAdd(&g_stats[2 * D + c0 + c], s);
            }
        }
        __syncthreads();
#pragma unroll
        for (int c = 0; c < 5; c++) dsc[ty * D + c0 + c] = (double)lsq[c];
        __syncthreads();
        if (ty == 0) {
#pragma unroll
            for (int c = 0; c < 5; c++) {
                double s = 0;
                for (int yy = 0; yy < 16; yy++) s += dsc[yy * D + c0 + c];
                atomicAdd(&g_stats[3 * D + c0 + c], s);
            }
        }
    }
}

// ---------------- hraw = (A + num/(den+eps))*snorm_n, + BN stats ----------------
__global__ void hcombine_kernel(const float* __restrict__ snorm, int Nn) {
    int j = threadIdx.x, ty = threadIdx.y;  // (70, 8)
    float ls = 0.f, lq = 0.f;
    for (int row = blockIdx.x * 8 + ty; row < Nn; row += gridDim.x * 8) {
        const float2 nd = *(const float2*)&g_nd[(size_t)row * 2 * D + 2 * j];
        size_t idx = (size_t)row * D + j;
        float v = (g_A[idx] + nd.x / (nd.y + 1e-6f)) * snorm[row];
        g_hraw[idx] = v;
        ls += v; lq += v * v;
    }
    __shared__ float s1[8][D];
    s1[ty][j] = ls;
    __syncthreads();
    if (ty == 0) {
        float s = ls;
        for (int yy = 1; yy < 8; yy++) s += s1[yy][j];
        atomicAdd(&g_stats[j], (double)s);
    }
    __syncthreads();
    s1[ty][j] = lq;
    __syncthreads();
    if (ty == 0) {
        float s = lq;
        for (int yy = 1; yy < 8; yy++) s += s1[yy][j];
        atomicAdd(&g_stats[D + j], (double)s);
    }
}

__global__ void finalize_kernel(int Nn, int E_) {
    int j = threadIdx.x;
    if (j < D) {
        double mu = g_stats[j] / Nn;
        double var = g_stats[D + j] / Nn - mu * mu;
        g_norm[j] = (float)mu;
        g_norm[D + j] = rsqrtf(fmaxf((float)var, 0.f) + 1e-5f);
        double mue = g_stats[2 * D + j] / E_;
        double vare = g_stats[3 * D + j] / E_ - mue * mue;
        g_norm[2 * D + j] = (float)mue;
        g_norm[3 * D + j] = rsqrtf(fmaxf((float)vare, 0.f) + 1e-5f);
    }
}

// ---------------- readout (fused final h-update) ----------------
__global__ void scatter_kernel(const int* __restrict__ gid,
                               const float* __restrict__ hgam, const float* __restrict__ hbet,
                               int Nn) {
    int j = threadIdx.x;
    float mu = g_norm[j], rs = g_norm[D + j], ga = hgam[j], bb = hbet[j];
    for (int row = blockIdx.x * 8 + threadIdx.y; row < Nn; row += gridDim.x * 8) {
        size_t idx = (size_t)row * D + j;
        float v = g_h[idx] + fmaxf((g_hraw[idx] - mu) * rs * ga + bb, 0.f);
        int g = gid[row];
        atomicAdd(&g_hg[g * D + j], v);
        if (j == 0) atomicAdd(&g_cnt[g], 1.f);
    }
}

__global__ void mlp_kernel(const float* __restrict__ W0, const float* __restrict__ b0,
                           const float* __restrict__ W1, const float* __restrict__ b1,
                           const float* __restrict__ W2, const float* __restrict__ b2,
                           float* __restrict__ out) {
    int g = threadIdx.x;
    if (g >= GG) return;
    float cnt = fmaxf(g_cnt[g], 1.f);
    float x[D];
#pragma unroll
    for (int k = 0; k < D; k++) x[k] = g_hg[g * D + k] / cnt;
    float y0[35];
#pragma unroll
    for (int o = 0; o < 35; o++) {
        float s = b0[o];
#pragma unroll
        for (int k = 0; k < D; k++) s += x[k] * W0[k * 35 + o];
        y0[o] = fmaxf(s, 0.f);
    }
    float y1[17];
#pragma unroll
    for (int o = 0; o < 17; o++) {
        float s = b1[o];
#pragma unroll
        for (int k = 0; k < 35; k++) s += y0[k] * W1[k * 17 + o];
        y1[o] = fmaxf(s, 0.f);
    }
#pragma unroll
    for (int o = 0; o < 10; o++) {
        float s = b2[o];
#pragma unroll
        for (int k = 0; k < 17; k++) s += y1[k] * W2[k * 10 + o];
        out[g * 10 + o] = s;
    }
}

// ---------------- host ----------------
extern "C" void kernel_launch(void* const* d_in, const int* in_sizes, int n_in,
                              void* d_out, int out_size) {
    const float* nodes   = (const float*)d_in[0];
    const float* ef      = (const float*)d_in[1];
    const float* snorm_n = (const float*)d_in[2];
    const float* snorm_e = (const float*)d_in[3];
    const int N = in_sizes[2];
    const int E_ = in_sizes[3];

    const int *src, *dst, *gid;
    const float *Wemb_h, *bemb_h, *Wemb_e, *bemb_e;
    const float *WA, *bA, *WB, *bB, *WC, *bC, *WDl, *bDl, *WEl, *bEl;
    const float *gh, *bh, *ge, *be, *W0, *b0, *W1, *b1, *W2, *b2;

    if (in_sizes[4] == E_) {
        src = (const int*)d_in[4]; dst = (const int*)d_in[5]; gid = (const int*)d_in[6];
        Wemb_h = (const float*)d_in[7];  bemb_h = (const float*)d_in[8];
        Wemb_e = (const float*)d_in[9];  bemb_e = (const float*)d_in[10];
        WA = (const float*)d_in[11]; bA = (const float*)d_in[12];
        WB = (const float*)d_in[13]; bB = (const float*)d_in[14];
        WC = (const float*)d_in[15]; bC = (const float*)d_in[16];
        WDl = (const float*)d_in[17]; bDl = (const float*)d_in[18];
        WEl = (const float*)d_in[19]; bEl = (const float*)d_in[20];
        gh = (const float*)d_in[21]; bh = (const float*)d_in[22];
        ge = (const float*)d_in[23]; be = (const float*)d_in[24];
        W0 = (const float*)d_in[25]; b0 = (const float*)d_in[26];
        W1 = (const float*)d_in[27]; b1 = (const float*)d_in[28];
        W2 = (const float*)d_in[29]; b2 = (const float*)d_in[30];
    } else {
        Wemb_h = (const float*)d_in[4];  bemb_h = (const float*)d_in[5];
        Wemb_e = (const float*)d_in[6];  bemb_e = (const float*)d_in[7];
        WA = (const float*)d_in[8];  bA = (const float*)d_in[9];
        WB = (const float*)d_in[10]; bB = (const float*)d_in[11];
        WC = (const float*)d_in[12]; bC = (const float*)d_in[13];
        WDl = (const float*)d_in[14]; bDl = (const float*)d_in[15];
        WEl = (const float*)d_in[16]; bEl = (const float*)d_in[17];
        gh = (const float*)d_in[18]; bh = (const float*)d_in[19];
        ge = (const float*)d_in[20]; be = (const float*)d_in[21];
        W0 = (const float*)d_in[22]; b0 = (const float*)d_in[23];
        W1 = (const float*)d_in[24]; b1 = (const float*)d_in[25];
        W2 = (const float*)d_in[26]; b2 = (const float*)d_in[27];
        src = (const int*)d_in[28]; dst = (const int*)d_in[29]; gid = (const int*)d_in[30];
    }
    float* out = (float*)d_out;

    float* ph;
    cudaGetSymbolAddress((void**)&ph, g_h);

    dim3 tb(14, 16);
    const int gemmBlocks = (N + 63) / 64;
    const size_t smem146 = (size_t)(146 * D + 64 * 146) * sizeof(float);
    const size_t smemEdge = (size_t)(128 * D + D * D) * sizeof(float);
    cudaFuncSetAttribute(gemm70_kernel<146>, cudaFuncAttributeMaxDynamicSharedMemorySize, (int)smem146);
    cudaFuncSetAttribute(edge_kernel<1, 1, 1>, cudaFuncAttributeMaxDynamicSharedMemorySize, (int)smemEdge);
    cudaFuncSetAttribute(edge_kernel<0, 1, 1>, cudaFuncAttributeMaxDynamicSharedMemorySize, (int)smemEdge);
    cudaFuncSetAttribute(edge_kernel<0, 0, 0>, cudaFuncAttributeMaxDynamicSharedMemorySize, (int)smemEdge);

    // precompute rank-1 Ce for layer 0 + node embedding
    uv_kernel<<<1, D>>>(Wemb_e, bemb_e, WC, bC);
    gemm70_kernel<146><<<gemmBlocks, tb, smem146>>>(nodes, Wemb_h, bemb_h, ph, N);

    const int edgeBlocks = 444;   // 148 SM * 3 (smem-limited)

    for (int l = 0; l < 4; l++) {
        const float* wA = WA + l * D * D; const float* biA = bA + l * D;
        const float* wB = WB + l * D * D; const float* biB = bB + l * D;
        const float* wC = WC + l * D * D; const float* biC = bC + l * D;
        const float* wD = WDl + l * D * D; const float* biD = bDl + l * D;
        const float* wE = WEl + l * D * D; const float* biE = bEl + l * D;

        zero_layer_kernel<<<2048, 256>>>(N * 2 * D);

        if (l == 0) {
            gemm4_kernel<<<gemmBlocks, tb>>>(wA, biA, wB, biB, wD, biD, wE, biE,
                                             nullptr, nullptr, 0, N);
            edge0_kernel<<<592, dim3(D, 8)>>>(ef, src, dst, snorm_e, E_);
        } else {
            gemm4_kernel<<<gemmBlocks, tb>>>(wA, biA, wB, biB, wD, biD, wE, biE,
                                             gh + (l - 1) * D, bh + (l - 1) * D, 1, N);
            const float* eg = ge + (l - 1) * D;
            const float* eb = be + (l - 1) * D;
            if (l == 1)
                edge_kernel<1, 1, 1><<<edgeBlocks, tb, smemEdge>>>(ef, wC, biC, Wemb_e, bemb_e,
                                                                   eg, eb, src, dst, snorm_e, E_);
            else if (l == 2)
                edge_kernel<0, 1, 1><<<edgeBlocks, tb, smemEdge>>>(ef, wC, biC, Wemb_e, bemb_e,
                                                                   eg, eb, src, dst, snorm_e, E_);
            else
                edge_kernel<0, 0, 0><<<edgeBlocks, tb, smemEdge>>>(ef, wC, biC, Wemb_e, bemb_e,
                                                                   eg, eb, src, dst, snorm_e, E_);
        }

        hcombine_kernel<<<1024, dim3(D, 8)>>>(snorm_n, N);
        finalize_kernel<<<1, D>>>(N, E_);
    }

    // readout (h-update of final layer fused into scatter)
    zero_readout_kernel<<<(GG * D + 255) / 256, 256>>>();
    scatter_kernel<<<(N + 7) / 8, dim3(D, 8)>>>(gid, gh + 3 * D, bh + 3 * D, N);
    mlp_kernel<<<1, GG>>>(W0, b0, W1, b1, W2, b2, out);
}

// round 3
// speedup vs baseline: 1.3792x; 1.3792x over previous
#include <cuda_runtime.h>
#include <math.h>

#define D 70
#define NMAX 50000
#define EMAX 800000
#define GG 128

// ---------------- device scratch ----------------
__device__ float g_h[NMAX * D];
__device__ float g_A[NMAX * D];
__device__ float g_B[NMAX * D];
__device__ float g_Dh[NMAX * D];
__device__ float g_Eh[NMAX * D];
__device__ float g_hraw[NMAX * D];
__device__ float g_S[EMAX * D];       // cumulative relu(bn(enew)) sum (permuted order)
__device__ float g_enew[EMAX * D];    // pre-BN edge activations (permuted order)
__device__ float g_ce[EMAX * D];      // per-layer edge GEMM output (permuted order)
__device__ double g_stats[4 * D];     // hsum, hsq, esum, esq
__device__ float g_norm[4 * D];       // mu_h, rstd_h, mu_e, rstd_e
__device__ float g_hg[GG * D];
__device__ float g_cnt[GG];
__device__ float g_u[D];              // rank-1 e0 contribution to Ce (per layer)
__device__ float g_v[D];
// CSR / permutation
__device__ int g_cnt_n[NMAX];
__device__ int g_rowoff[NMAX + 1];
__device__ int g_psrc[EMAX];
__device__ float g_pef[EMAX];
__device__ float g_psn[EMAX];

// ---------------- sort: histogram / scan / scatter ----------------
__global__ void hist_zero_kernel(int Nn) {
    int i = blockIdx.x * blockDim.x + threadIdx.x;
    if (i < Nn) g_cnt_n[i] = 0;
    if (i < 4 * D) g_stats[i] = 0.0;
}

__global__ void hist_kernel(const int* __restrict__ dst, int E_) {
    int i = blockIdx.x * blockDim.x + threadIdx.x;
    if (i < E_) atomicAdd(&g_cnt_n[dst[i]], 1);
}

__global__ void scan_kernel(int Nn, int E_) {
    __shared__ int s[1024];
    int t = threadIdx.x;
    int chunk = (Nn + 1023) / 1024;
    int begin = t * chunk, end = min(begin + chunk, Nn);
    int sum = 0;
    for (int i = begin; i < end; i++) sum += g_cnt_n[i];
    s[t] = sum;
    __syncthreads();
    for (int off = 1; off < 1024; off <<= 1) {
        int tmp = (t >= off) ? s[t - off] : 0;
        __syncthreads();
        s[t] += tmp;
        __syncthreads();
    }
    int acc = s[t] - sum;  // exclusive prefix for this chunk
    for (int i = begin; i < end; i++) {
        int c = g_cnt_n[i];
        g_rowoff[i] = acc;
        acc += c;
        g_cnt_n[i] = 0;  // reset as scatter cursor
    }
    if (t == 0) g_rowoff[Nn] = E_;
}

__global__ void scatter_sort_kernel(const int* __restrict__ src, const int* __restrict__ dst,
                                    const float* __restrict__ ef, const float* __restrict__ sn,
                                    int E_) {
    int i = blockIdx.x * blockDim.x + threadIdx.x;
    if (i < E_) {
        int d = dst[i];
        int pos = g_rowoff[d] + atomicAdd(&g_cnt_n[d], 1);
        g_psrc[pos] = src[i];
        g_pef[pos] = ef[i];
        g_psn[pos] = sn[i];
    }
}

// ---------------- rank-1 layer Ce precompute ----------------
__global__ void uv_kernel(const float* __restrict__ WembE, const float* __restrict__ bembE,
                          const float* __restrict__ WC, const float* __restrict__ bC) {
    int j = threadIdx.x;
    if (j >= D) return;
    float u = 0.f, v = 0.f;
    for (int k = 0; k < D; k++) {
        float w = WC[k * D + j];
        u += WembE[k] * w;
        v += bembE[k] * w;
    }
    g_u[j] = u;
    g_v[j] = v + bC[j];
}

// ---------------- embedding GEMM [N,146]@[146,70] ----------------
template <int K>
__global__ void gemm70_kernel(const float* __restrict__ X, const float* __restrict__ W,
                              const float* __restrict__ bias, float* __restrict__ Y, int M) {
    extern __shared__ float smem[];
    float* sW = smem;
    float* sX = smem + K * D;
    __shared__ float sb[D];
    const int tx = threadIdx.x, ty = threadIdx.y;
    const int tid = ty * 14 + tx;
    for (int i = tid; i < K * D; i += 224) sW[i] = W[i];
    if (tid < D) sb[tid] = bias[tid];
    __syncthreads();

    const int base = blockIdx.x * 64;
    const int cnt = min(64, M - base);
    for (int i = tid; i < cnt * K; i += 224) sX[i] = X[(size_t)base * K + i];
    __syncthreads();

    const int c0 = tx * 5, r0 = ty * 4;
    float acc[4][5];
#pragma unroll
    for (int r = 0; r < 4; r++)
#pragma unroll
        for (int c = 0; c < 5; c++) acc[r][c] = sb[c0 + c];

#pragma unroll 2
    for (int k = 0; k < K; k++) {
        float w0 = sW[k * D + c0 + 0], w1 = sW[k * D + c0 + 1], w2 = sW[k * D + c0 + 2];
        float w3 = sW[k * D + c0 + 3], w4 = sW[k * D + c0 + 4];
#pragma unroll
        for (int r = 0; r < 4; r++) {
            float xv = (r0 + r < cnt) ? sX[(r0 + r) * K + k] : 0.f;
            acc[r][0] += xv * w0; acc[r][1] += xv * w1; acc[r][2] += xv * w2;
            acc[r][3] += xv * w3; acc[r][4] += xv * w4;
        }
    }
#pragma unroll
    for (int r = 0; r < 4; r++) {
        int row = base + r0 + r;
        if (row < M) {
#pragma unroll
            for (int c = 0; c < 5; c++) Y[(size_t)row * D + c0 + c] = acc[r][c];
        }
    }
}

// ---------------- fused node kernel: optional h-update + 4 GEMMs ----------------
__global__ __launch_bounds__(224) void gemm4_kernel(
    const float* __restrict__ WA, const float* __restrict__ bA,
    const float* __restrict__ WB, const float* __restrict__ bB,
    const float* __restrict__ WD, const float* __restrict__ bD,
    const float* __restrict__ WE, const float* __restrict__ bE,
    const float* __restrict__ hgam, const float* __restrict__ hbet,
    int fuse, int Nn) {
    __shared__ float sX[64 * D];
    __shared__ float sW[D * D];
    __shared__ float sb[D];
    __shared__ float sMu[D], sRs[D], sGa[D], sBe[D];
    const int tx = threadIdx.x, ty = threadIdx.y;
    const int tid = ty * 14 + tx;
    if (fuse && tid < D) {
        sMu[tid] = g_norm[tid];
        sRs[tid] = g_norm[D + tid];
        sGa[tid] = hgam[tid];
        sBe[tid] = hbet[tid];
    }
    const int base = blockIdx.x * 64;
    const int cnt = min(64, Nn - base);
    __syncthreads();
    for (int idx = tid; idx < cnt * D; idx += 224) {
        size_t gi = (size_t)base * D + idx;
        float v = g_h[gi];
        if (fuse) {
            int r = idx / D;
            int c = idx - r * D;
            float hr = g_hraw[gi];
            v += fmaxf((hr - sMu[c]) * sRs[c] * sGa[c] + sBe[c], 0.f);
            g_h[gi] = v;
        }
        sX[idx] = v;
    }
    if (cnt < 64)
        for (int idx = cnt * D + tid; idx < 64 * D; idx += 224) sX[idx] = 0.f;

    const float* Ws[4] = {WA, WB, WD, WE};
    const float* bs[4] = {bA, bB, bD, bE};
    float* outs[4] = {g_A, g_B, g_Dh, g_Eh};

    const int c0 = tx * 5, r0 = ty * 4;
    for (int m = 0; m < 4; m++) {
        __syncthreads();
        for (int i = tid; i < D * D; i += 224) sW[i] = Ws[m][i];
        if (tid < D) sb[tid] = bs[m][tid];
        __syncthreads();

        float acc[4][5];
#pragma unroll
        for (int r = 0; r < 4; r++)
#pragma unroll
            for (int c = 0; c < 5; c++) acc[r][c] = sb[c0 + c];

#pragma unroll 2
        for (int k = 0; k < D; k++) {
            float w0 = sW[k * D + c0 + 0], w1 = sW[k * D + c0 + 1], w2 = sW[k * D + c0 + 2];
            float w3 = sW[k * D + c0 + 3], w4 = sW[k * D + c0 + 4];
#pragma unroll
            for (int r = 0; r < 4; r++) {
                float xv = sX[(r0 + r) * D + k];
                acc[r][0] += xv * w0; acc[r][1] += xv * w1; acc[r][2] += xv * w2;
                acc[r][3] += xv * w3; acc[r][4] += xv * w4;
            }
        }
        float* out = outs[m];
#pragma unroll
        for (int r = 0; r < 4; r++) {
            int row = base + r0 + r;
            if (row < Nn) {
#pragma unroll
                for (int c = 0; c < 5; c++) out[(size_t)row * D + c0 + c] = acc[r][c];
            }
        }
    }
}

// ---------------- streaming edge GEMM: ce = S_new@WC + ef*u + v ----------------
// S_new = (FIRST ? 0 : S) + relu(bn(enew_prev)); optionally write S_new back.
template <int FIRST, int WRITE_S>
__global__ __launch_bounds__(224) void edgegemm_kernel(
    const float* __restrict__ WC,
    const float* __restrict__ egam, const float* __restrict__ ebet, int E_) {
    extern __shared__ __align__(16) float dsm[];
    float* sW = dsm;             // 70*70
    float* sX = dsm + D * D;     // 128*70
    __shared__ float sef[128];
    __shared__ float su[D], sv[D], sMu[D], sRs[D], sGa[D], sBe[D];
    const int tx = threadIdx.x, ty = threadIdx.y;
    const int tid = ty * 14 + tx;
    for (int i = tid; i < D * D; i += 224) sW[i] = WC[i];
    if (tid < D) {
        su[tid] = g_u[tid];
        sv[tid] = g_v[tid];
        sMu[tid] = g_norm[2 * D + tid];
        sRs[tid] = g_norm[3 * D + tid];
        sGa[tid] = egam[tid];
        sBe[tid] = ebet[tid];
    }
    __syncthreads();

    const int base = blockIdx.x * 128;
    const int cnt = min(128, E_ - base);
    for (int idx = tid; idx < cnt * D; idx += 224) {
        size_t gi = (size_t)base * D + idx;
        int r = idx / D;
        int c = idx - r * D;
        float R = fmaxf((g_enew[gi] - sMu[c]) * sRs[c] * sGa[c] + sBe[c], 0.f);
        float Sv = FIRST ? R : (g_S[gi] + R);
        sX[idx] = Sv;
        if (WRITE_S) g_S[gi] = Sv;
    }
    if (cnt < 128)
        for (int idx = cnt * D + tid; idx < 128 * D; idx += 224) sX[idx] = 0.f;
    for (int i = tid; i < 128; i += 224) sef[i] = (i < cnt) ? g_pef[base + i] : 0.f;
    __syncthreads();

    const int c0 = tx * 5, r0 = ty * 8;
    float acc[8][5];
#pragma unroll
    for (int r = 0; r < 8; r++) {
        float efv = sef[r0 + r];
#pragma unroll
        for (int c = 0; c < 5; c++) acc[r][c] = sv[c0 + c] + efv * su[c0 + c];
    }

#pragma unroll 2
    for (int k = 0; k < D; k++) {
        float w0 = sW[k * D + c0 + 0], w1 = sW[k * D + c0 + 1], w2 = sW[k * D + c0 + 2];
        float w3 = sW[k * D + c0 + 3], w4 = sW[k * D + c0 + 4];
#pragma unroll
        for (int r = 0; r < 8; r++) {
            float xv = sX[(r0 + r) * D + k];
            acc[r][0] += xv * w0; acc[r][1] += xv * w1; acc[r][2] += xv * w2;
            acc[r][3] += xv * w3; acc[r][4] += xv * w4;
        }
    }
#pragma unroll
    for (int r = 0; r < 8; r++) {
        int ei = base + r0 + r;
        if (ei < E_) {
#pragma unroll
            for (int c = 0; c < 5; c++) g_ce[(size_t)ei * D + c0 + c] = acc[r][c];
        }
    }
}

// ---------------- node-centric aggregation (no atomics) ----------------
// For each node n, col j: walk CSR edges, en = ce + Dh[src] + Eh[n]; sigmoid;
// accumulate num/den in regs; write enew (unless LAST); produce hraw + all BN stats.
template <int RANK1, int LAST>
__global__ __launch_bounds__(560) void agg_kernel(const float* __restrict__ snorm_n, int Nn) {
    int j = threadIdx.x, ty = threadIdx.y;  // (70, 8)
    float u = g_u[j], v = g_v[j];
    float lsE = 0.f, lqE = 0.f, lsH = 0.f, lqH = 0.f;
    for (int n = blockIdx.x * 8 + ty; n < Nn; n += gridDim.x * 8) {
        float eh = g_Eh[(size_t)n * D + j];
        int e0 = g_rowoff[n], e1 = g_rowoff[n + 1];
        float num = 0.f, den = 0.f;
        for (int e = e0; e < e1; e++) {
            int s = g_psrc[e];
            float ce;
            if (RANK1) ce = g_pef[e] * u + v;
            else       ce = g_ce[(size_t)e * D + j];
            float en = ce + g_Dh[(size_t)s * D + j] + eh;
            float sg = 1.f / (1.f + __expf(-en));
            num += g_B[(size_t)s * D + j] * sg;
            den += sg;
            if (!LAST) {
                float ens = en * g_psn[e];
                g_enew[(size_t)e * D + j] = ens;
                lsE += ens; lqE += ens * ens;
            }
        }
        size_t idx = (size_t)n * D + j;
        float hv = (g_A[idx] + num / (den + 1e-6f)) * snorm_n[n];
        g_hraw[idx] = hv;
        lsH += hv; lqH += hv * hv;
    }
    __shared__ float s1[8][D];
    s1[ty][j] = lsH;
    __syncthreads();
    if (ty == 0) {
        float s = lsH;
        for (int yy = 1; yy < 8; yy++) s += s1[yy][j];
        atomicAdd(&g_stats[j], (double)s);
    }
    __syncthreads();
    s1[ty][j] = lqH;
    __syncthreads();
    if (ty == 0) {
        float s = lqH;
        for (int yy = 1; yy < 8; yy++) s += s1[yy][j];
        atomicAdd(&g_stats[D + j], (double)s);
    }
    if (!LAST) {
        __syncthreads();
        s1[ty][j] = lsE;
        __syncthreads();
        if (ty == 0) {
            float s = lsE;
            for (int yy = 1; yy < 8; yy++) s += s1[yy][j];
            atomicAdd(&g_stats[2 * D + j], (double)s);
        }
        __syncthreads();
        s1[ty][j] = lqE;
        __syncthreads();
        if (ty == 0) {
            float s = lqE;
            for (int yy = 1; yy < 8; yy++) s += s1[yy][j];
            atomicAdd(&g_stats[3 * D + j], (double)s);
        }
    }
}

__global__ void finalize_kernel(int Nn, int E_) {
    int j = threadIdx.x;
    if (j < D) {
        double mu = g_stats[j] / Nn;
        double var = g_stats[D + j] / Nn - mu * mu;
        g_norm[j] = (float)mu;
        g_norm[D + j] = rsqrtf(fmaxf((float)var, 0.f) + 1e-5f);
        double mue = g_stats[2 * D + j] / E_;
        double vare = g_stats[3 * D + j] / E_ - mue * mue;
        g_norm[2 * D + j] = (float)mue;
        g_norm[3 * D + j] = rsqrtf(fmaxf((float)vare, 0.f) + 1e-5f);
        g_stats[j] = 0.0;
        g_stats[D + j] = 0.0;
        g_stats[2 * D + j] = 0.0;
        g_stats[3 * D + j] = 0.0;
    }
}

// ---------------- readout ----------------
__global__ void zero_readout_kernel() {
    int i = blockIdx.x * blockDim.x + threadIdx.x;
    if (i < GG * D) g_hg[i] = 0.f;
    if (i < GG) g_cnt[i] = 0.f;
}

__global__ void scatter_kernel(const int* __restrict__ gid,
                               const float* __restrict__ hgam, const float* __restrict__ hbet,
                               int Nn) {
    int j = threadIdx.x;
    float mu = g_norm[j], rs = g_norm[D + j], ga = hgam[j], bb = hbet[j];
    for (int row = blockIdx.x * 8 + threadIdx.y; row < Nn; row += gridDim.x * 8) {
        size_t idx = (size_t)row * D + j;
        float v = g_h[idx] + fmaxf((g_hraw[idx] - mu) * rs * ga + bb, 0.f);
        int g = gid[row];
        atomicAdd(&g_hg[g * D + j], v);
        if (j == 0) atomicAdd(&g_cnt[g], 1.f);
    }
}

__global__ void mlp_kernel(const float* __restrict__ W0, const float* __restrict__ b0,
                           const float* __restrict__ W1, const float* __restrict__ b1,
                           const float* __restrict__ W2, const float* __restrict__ b2,
                           float* __restrict__ out) {
    int g = threadIdx.x;
    if (g >= GG) return;
    float cnt = fmaxf(g_cnt[g], 1.f);
    float x[D];
#pragma unroll
    for (int k = 0; k < D; k++) x[k] = g_hg[g * D + k] / cnt;
    float y0[35];
#pragma unroll
    for (int o = 0; o < 35; o++) {
        float s = b0[o];
#pragma unroll
        for (int k = 0; k < D; k++) s += x[k] * W0[k * 35 + o];
        y0[o] = fmaxf(s, 0.f);
    }
    float y1[17];
#pragma unroll
    for (int o = 0; o < 17; o++) {
        float s = b1[o];
#pragma unroll
        for (int k = 0; k < 35; k++) s += y0[k] * W1[k * 17 + o];
        y1[o] = fmaxf(s, 0.f);
    }
#pragma unroll
    for (int o = 0; o < 10; o++) {
        float s = b2[o];
#pragma unroll
        for (int k = 0; k < 17; k++) s += y1[k] * W2[k * 10 + o];
        out[g * 10 + o] = s;
    }
}

// ---------------- host ----------------
extern "C" void kernel_launch(void* const* d_in, const int* in_sizes, int n_in,
                              void* d_out, int out_size) {
    const float* nodes   = (const float*)d_in[0];
    const float* ef      = (const float*)d_in[1];
    const float* snorm_n = (const float*)d_in[2];
    const float* snorm_e = (const float*)d_in[3];
    const int N = in_sizes[2];
    const int E_ = in_sizes[3];

    const int *src, *dst, *gid;
    const float *Wemb_h, *bemb_h, *Wemb_e, *bemb_e;
    const float *WA, *bA, *WB, *bB, *WC, *bC, *WDl, *bDl, *WEl, *bEl;
    const float *gh, *bh, *ge, *be, *W0, *b0, *W1, *b1, *W2, *b2;

    if (in_sizes[4] == E_) {
        src = (const int*)d_in[4]; dst = (const int*)d_in[5]; gid = (const int*)d_in[6];
        Wemb_h = (const float*)d_in[7];  bemb_h = (const float*)d_in[8];
        Wemb_e = (const float*)d_in[9];  bemb_e = (const float*)d_in[10];
        WA = (const float*)d_in[11]; bA = (const float*)d_in[12];
        WB = (const float*)d_in[13]; bB = (const float*)d_in[14];
        WC = (const float*)d_in[15]; bC = (const float*)d_in[16];
        WDl = (const float*)d_in[17]; bDl = (const float*)d_in[18];
        WEl = (const float*)d_in[19]; bEl = (const float*)d_in[20];
        gh = (const float*)d_in[21]; bh = (const float*)d_in[22];
        ge = (const float*)d_in[23]; be = (const float*)d_in[24];
        W0 = (const float*)d_in[25]; b0 = (const float*)d_in[26];
        W1 = (const float*)d_in[27]; b1 = (const float*)d_in[28];
        W2 = (const float*)d_in[29]; b2 = (const float*)d_in[30];
    } else {
        Wemb_h = (const float*)d_in[4];  bemb_h = (const float*)d_in[5];
        Wemb_e = (const float*)d_in[6];  bemb_e = (const float*)d_in[7];
        WA = (const float*)d_in[8];  bA = (const float*)d_in[9];
        WB = (const float*)d_in[10]; bB = (const float*)d_in[11];
        WC = (const float*)d_in[12]; bC = (const float*)d_in[13];
        WDl = (const float*)d_in[14]; bDl = (const float*)d_in[15];
        WEl = (const float*)d_in[16]; bEl = (const float*)d_in[17];
        gh = (const float*)d_in[18]; bh = (const float*)d_in[19];
        ge = (const float*)d_in[20]; be = (const float*)d_in[21];
        W0 = (const float*)d_in[22]; b0 = (const float*)d_in[23];
        W1 = (const float*)d_in[24]; b1 = (const float*)d_in[25];
        W2 = (const float*)d_in[26]; b2 = (const float*)d_in[27];
        src = (const int*)d_in[28]; dst = (const int*)d_in[29]; gid = (const int*)d_in[30];
    }
    float* out = (float*)d_out;

    float* ph;
    cudaGetSymbolAddress((void**)&ph, g_h);

    dim3 tb(14, 16);
    const int gemmBlocks = (N + 63) / 64;
    const size_t smem146 = (size_t)(146 * D + 64 * 146) * sizeof(float);
    const size_t smemEG = (size_t)(D * D + 128 * D) * sizeof(float);
    cudaFuncSetAttribute(gemm70_kernel<146>, cudaFuncAttributeMaxDynamicSharedMemorySize, (int)smem146);
    cudaFuncSetAttribute(edgegemm_kernel<1, 1>, cudaFuncAttributeMaxDynamicSharedMemorySize, (int)smemEG);
    cudaFuncSetAttribute(edgegemm_kernel<0, 1>, cudaFuncAttributeMaxDynamicSharedMemorySize, (int)smemEG);
    cudaFuncSetAttribute(edgegemm_kernel<0, 0>, cudaFuncAttributeMaxDynamicSharedMemorySize, (int)smemEG);

    // per-launch counting sort of edges by dst (+ zero stats)
    hist_zero_kernel<<<(N + 255) / 256, 256>>>(N);
    hist_kernel<<<(E_ + 255) / 256, 256>>>(dst, E_);
    scan_kernel<<<1, 1024>>>(N, E_);
    scatter_sort_kernel<<<(E_ + 255) / 256, 256>>>(src, dst, ef, snorm_e, E_);

    // node embedding
    gemm70_kernel<146><<<gemmBlocks, tb, smem146>>>(nodes, Wemb_h, bemb_h, ph, N);

    const int egBlocks = (E_ + 127) / 128;

    for (int l = 0; l < 4; l++) {
        const float* wA = WA + l * D * D; const float* biA = bA + l * D;
        const float* wB = WB + l * D * D; const float* biB = bB + l * D;
        const float* wC = WC + l * D * D; const float* biC = bC + l * D;
        const float* wD = WDl + l * D * D; const float* biD = bDl + l * D;
        const float* wE = WEl + l * D * D; const float* biE = bEl + l * D;

        uv_kernel<<<1, D>>>(Wemb_e, bemb_e, wC, biC);

        if (l == 0) {
            gemm4_kernel<<<gemmBlocks, tb>>>(wA, biA, wB, biB, wD, biD, wE, biE,
                                             nullptr, nullptr, 0, N);
            agg_kernel<1, 0><<<1024, dim3(D, 8)>>>(snorm_n, N);
        } else {
            gemm4_kernel<<<gemmBlocks, tb>>>(wA, biA, wB, biB, wD, biD, wE, biE,
                                             gh + (l - 1) * D, bh + (l - 1) * D, 1, N);
            const float* eg = ge + (l - 1) * D;
            const float* eb = be + (l - 1) * D;
            if (l == 1)
                edgegemm_kernel<1, 1><<<egBlocks, tb, smemEG>>>(wC, eg, eb, E_);
            else if (l == 2)
                edgegemm_kernel<0, 1><<<egBlocks, tb, smemEG>>>(wC, eg, eb, E_);
            else
                edgegemm_kernel<0, 0><<<egBlocks, tb, smemEG>>>(wC, eg, eb, E_);

            if (l == 3)
                agg_kernel<0, 1><<<1024, dim3(D, 8)>>>(snorm_n, N);
            else
                agg_kernel<0, 0><<<1024, dim3(D, 8)>>>(snorm_n, N);
        }
        finalize_kernel<<<1, D>>>(N, E_);
    }

    // readout (final h-update fused into scatter)
    zero_readout_kernel<<<(GG * D + 255) / 256, 256>>>();
    scatter_kernel<<<(N + 7) / 8, dim3(D, 8)>>>(gid, gh + 3 * D, bh + 3 * D, N);
    mlp_kernel<<<1, GG>>>(W0, b0, W1, b1, W2, b2, out);
}